// round 2
// baseline (speedup 1.0000x reference)
#include <cuda_runtime.h>
#include <math.h>
#include <float.h>
#include <stdint.h>

#define BB 16
#define DD 512
#define TT 2048
#define NQ 9
#define CS 1024
#define CD 8
#define TTILE 64
#define NTHREADS 512

typedef unsigned long long ull;

__device__ __forceinline__ ull pk2(float lo, float hi) {
    ull r; asm("mov.b64 %0,{%1,%2};" : "=l"(r) : "f"(lo), "f"(hi)); return r;
}
__device__ __forceinline__ void upk2(float& lo, float& hi, ull v) {
    asm("mov.b64 {%0,%1},%2;" : "=f"(lo), "=f"(hi) : "l"(v));
}
__device__ __forceinline__ ull fma2(ull a, ull b, ull c) {
    ull d; asm("fma.rn.f32x2 %0,%1,%2,%3;" : "=l"(d) : "l"(a), "l"(b), "l"(c)); return d;
}
__device__ __forceinline__ ull mul2(ull a, ull b) {
    ull d; asm("mul.rn.f32x2 %0,%1,%2;" : "=l"(d) : "l"(a), "l"(b)); return d;
}
__device__ __forceinline__ ull add2(ull a, ull b) {
    ull d; asm("add.rn.f32x2 %0,%1,%2;" : "=l"(d) : "l"(a), "l"(b)); return d;
}

// ---------------- precomputed (normalized) parameter scratch ----------------
__device__ float g_win[NQ * CD * DD];    // weight-normed in_proj  (q, c, d)
__device__ float g_woutT[NQ * CD * DD];  // weight-normed out_proj TRANSPOSED (q, c, d)
__device__ float g_cbn[NQ * CS * CD];    // l2-normalized codebook
__device__ float g_csq[NQ * CS];         // sum(c_norm^2) per code

__global__ void rvq_precompute(const float* __restrict__ iv, const float* __restrict__ ig,
                               const float* __restrict__ ov, const float* __restrict__ og,
                               const float* __restrict__ cb) {
    int q = blockIdx.x;
    int tid = threadIdx.x;           // 256 threads
    int wid = tid >> 5, lane = tid & 31;

    // in_proj: 8 rows of 512, one warp per row
    if (wid < CD) {
        int c = wid;
        const float* v = iv + ((size_t)q * CD + c) * DD;
        float ss = 0.f;
        for (int d = lane; d < DD; d += 32) { float x = v[d]; ss = fmaf(x, x, ss); }
        #pragma unroll
        for (int o = 16; o > 0; o >>= 1) ss += __shfl_xor_sync(0xffffffffu, ss, o);
        float nrm = __fsqrt_rn(ss);
        float g = ig[q * CD + c];
        for (int d = lane; d < DD; d += 32)
            g_win[((size_t)q * CD + c) * DD + d] = __fdiv_rn(g * v[d], nrm);
    }
    // out_proj: 512 rows of 8; store TRANSPOSED (c-major rows of 512 d)
    for (int r = tid; r < DD; r += 256) {
        const float* v = ov + ((size_t)q * DD + r) * CD;
        float ss = 0.f;
        #pragma unroll
        for (int c = 0; c < CD; c++) { float x = v[c]; ss = fmaf(x, x, ss); }
        float nrm = __fsqrt_rn(ss);
        float g = og[q * DD + r];
        #pragma unroll
        for (int c = 0; c < CD; c++)
            g_woutT[((size_t)q * CD + c) * DD + r] = __fdiv_rn(g * v[c], nrm);
    }
    // codebook: 1024 rows of 8, l2norm with eps, plus csq
    for (int s = tid; s < CS; s += 256) {
        const float* v = cb + ((size_t)q * CS + s) * CD;
        float ss = 0.f;
        #pragma unroll
        for (int c = 0; c < CD; c++) { float x = v[c]; ss = fmaf(x, x, ss); }
        float den = fmaxf(__fsqrt_rn(ss), 1e-12f);
        float cs2 = 0.f;
        #pragma unroll
        for (int c = 0; c < CD; c++) {
            float cn = __fdiv_rn(v[c], den);
            g_cbn[((size_t)q * CS + s) * CD + c] = cn;
            cs2 = fmaf(cn, cn, cs2);
        }
        g_csq[q * CS + s] = cs2;
    }
}

// ---------------- main fused RVQ kernel ----------------
#define RPITCH 518   // rest row pitch (floats): 2*259, odd*2 -> 2-way-max 8B bank spread
#define WPITCH 520   // win row pitch: mult of 4 for float4/ulonglong2 alignment

struct SMem {
    float4 cbn4[CS * 2];         // 32768 B  normalized codebook
    float  rest[TTILE * RPITCH]; // 132608 B residual, TRANSPOSED [t][d]
    float  win[CD][WPITCH];      // 16640 B
    float  woutT[CD][DD];        // 16384 B  transposed out weights [c][d]
    float  csq[CS];              // 4096 B
    float  ob[DD];               // 2048 B
    float  enc[CD][68];          // 2176 B  (pitch 68 -> bank 4c+t, conflict-free)
    float  zqs[CD][68];          // 2176 B
    float  encsq[TTILE];         // 256 B
    float  redb[16][68];         // 4352 B
    int    redi[16][68];         // 4352 B
    int    idx[TTILE];           // 256 B
    float  ib[CD];               // 32 B
};  // ~218 KB

__global__ void __launch_bounds__(NTHREADS, 1)
rvq_kernel(const float* __restrict__ z,
           const float* __restrict__ ib_g,
           const float* __restrict__ ob_g,
           const float* __restrict__ cbraw,
           float* __restrict__ out) {
    extern __shared__ unsigned char smraw[];
    SMem& sm = *reinterpret_cast<SMem*>(smraw);

    const int tid = threadIdx.x;
    const int b = blockIdx.y;
    const int t0 = blockIdx.x * TTILE;

    float* out_codes = out;
    float* out_zO  = out + (size_t)BB * NQ * TT;
    float* out_zis = out_zO + (size_t)BB * DD * TT;
    float* out_zqs = out_zis + (size_t)BB * NQ * CD * TT;
    float* out_zos = out_zqs + (size_t)BB * NQ * CD * TT;

    // ---- load residual tile, transposed into rest[t][d] ----
    const float* zb = z + (size_t)b * DD * TT + t0;
    for (int f = tid; f < DD * (TTILE / 4); f += NTHREADS) {
        int d = f >> 4, j = f & 15;
        float4 v = reinterpret_cast<const float4*>(zb + (size_t)d * TT)[j];
        int t = 4 * j;
        sm.rest[(t + 0) * RPITCH + d] = v.x;
        sm.rest[(t + 1) * RPITCH + d] = v.y;
        sm.rest[(t + 2) * RPITCH + d] = v.z;
        sm.rest[(t + 3) * RPITCH + d] = v.w;
    }

    // mapping A: c = tid&7, t = tid>>3   (warp holds all 8 c for 4 t -> shuffle norm)
    const int cA = tid & 7;
    const int tA = tid >> 3;
    // mapping C (NN): ch = tid>>5 (16 chunks of 64 codes), tp = tid&31 (2 t each)
    const int ch = tid >> 5;
    const int tp = tid & 31;
    // mapping E (z_o / zO): tE = tid&63, dg = tid>>6 (8 groups of 64 d)
    const int tE = tid & 63;
    const int dg = tid >> 6;

    float ziv = 0.f;   // carried register: this thread's z_i[cA][tA]

    for (int q = 0; q < NQ; q++) {
        __syncthreads();   // res settled, previous tables free
        // ---- load per-quantizer tables ----
        {
            const float4* s1 = reinterpret_cast<const float4*>(g_win + (size_t)q * CD * DD);
            for (int i = tid; i < CD * DD / 4; i += NTHREADS) {
                int c = i >> 7, j = i & 127;
                *reinterpret_cast<float4*>(&sm.win[c][4 * j]) = s1[i];
            }
            const float4* s2 = reinterpret_cast<const float4*>(g_woutT + (size_t)q * CD * DD);
            float4* d2 = reinterpret_cast<float4*>(&sm.woutT[0][0]);
            for (int i = tid; i < CD * DD / 4; i += NTHREADS) d2[i] = s2[i];
            const float4* s3 = reinterpret_cast<const float4*>(g_cbn + (size_t)q * CS * CD);
            for (int i = tid; i < CS * 2; i += NTHREADS) sm.cbn4[i] = s3[i];
            const float4* s4 = reinterpret_cast<const float4*>(g_csq + (size_t)q * CS);
            float4* d4 = reinterpret_cast<float4*>(&sm.csq[0]);
            for (int i = tid; i < CS / 4; i += NTHREADS) d4[i] = s4[i];
            const float4* s5 = reinterpret_cast<const float4*>(ob_g + (size_t)q * DD);
            float4* d5 = reinterpret_cast<float4*>(&sm.ob[0]);
            for (int i = tid; i < DD / 4; i += NTHREADS) d5[i] = s5[i];
            if (tid < CD) sm.ib[tid] = ib_g[q * CD + tid];
        }
        __syncthreads();

        // ---- z_i (packed over d-pairs) + shuffle L2-norm ----
        {
            const float* wrow = sm.win[cA];
            const float* rrow = &sm.rest[tA * RPITCH];
            ull a0 = 0ull, a1 = 0ull;
            #pragma unroll 8
            for (int d = 0; d < DD; d += 4) {
                ulonglong2 w2 = *reinterpret_cast<const ulonglong2*>(wrow + d);
                ull r01 = *reinterpret_cast<const ull*>(rrow + d);
                ull r23 = *reinterpret_cast<const ull*>(rrow + d + 2);
                a0 = fma2(w2.x, r01, a0);
                a1 = fma2(w2.y, r23, a1);
            }
            float l0, h0, l1, h1;
            upk2(l0, h0, a0); upk2(l1, h1, a1);
            ziv = ((l0 + h0) + (l1 + h1)) + sm.ib[cA];
            out_zis[(((size_t)b * NQ + q) * CD + cA) * TT + t0 + tA] = ziv;

            // norm across c (lanes 0..7 of each t within the warp)
            float ss = ziv * ziv;
            ss += __shfl_xor_sync(0xffffffffu, ss, 1);
            ss += __shfl_xor_sync(0xffffffffu, ss, 2);
            ss += __shfl_xor_sync(0xffffffffu, ss, 4);
            float den = fmaxf(__fsqrt_rn(ss), 1e-12f);
            float e = __fdiv_rn(ziv, den);
            float es = e * e;
            es += __shfl_xor_sync(0xffffffffu, es, 1);
            es += __shfl_xor_sync(0xffffffffu, es, 2);
            es += __shfl_xor_sync(0xffffffffu, es, 4);
            sm.enc[cA][tA] = e;
            if (cA == 0) sm.encsq[tA] = es;
        }
        __syncthreads();

        // ---- NN search: 16 chunks x 2 t per thread, packed over c-pairs ----
        {
            float e0[8], e1[8];
            #pragma unroll
            for (int c = 0; c < CD; c++) {
                e0[c] = sm.enc[c][2 * tp];
                e1[c] = sm.enc[c][2 * tp + 1];
            }
            ull ea[4], eb[4];
            #pragma unroll
            for (int j = 0; j < 4; j++) {
                ea[j] = pk2(e0[2 * j], e0[2 * j + 1]);
                eb[j] = pk2(e1[2 * j], e1[2 * j + 1]);
            }
            const float eqa = sm.encsq[2 * tp];
            const float eqb = sm.encsq[2 * tp + 1];
            const ulonglong2* cb8 = reinterpret_cast<const ulonglong2*>(sm.cbn4);

            float bA0 = FLT_MAX, bA1 = FLT_MAX, bB0 = FLT_MAX, bB1 = FLT_MAX;
            int   iA0 = 0, iA1 = 0, iB0 = 0, iB1 = 0;
            const int sBeg = ch * (CS / 16);
            #pragma unroll 4
            for (int s = sBeg; s < sBeg + CS / 16; s += 2) {
                ulonglong2 A0 = cb8[2 * s],     A1 = cb8[2 * s + 1];
                ulonglong2 B0 = cb8[2 * s + 2], B1 = cb8[2 * s + 3];
                float csA = sm.csq[s], csB = sm.csq[s + 1];

                ull dAa = fma2(ea[0], A0.x, fma2(ea[1], A0.y, fma2(ea[2], A1.x, mul2(ea[3], A1.y))));
                ull dAb = fma2(eb[0], A0.x, fma2(eb[1], A0.y, fma2(eb[2], A1.x, mul2(eb[3], A1.y))));
                ull dBa = fma2(ea[0], B0.x, fma2(ea[1], B0.y, fma2(ea[2], B1.x, mul2(ea[3], B1.y))));
                ull dBb = fma2(eb[0], B0.x, fma2(eb[1], B0.y, fma2(eb[2], B1.x, mul2(eb[3], B1.y))));

                float lo, hi;
                upk2(lo, hi, dAa); float distA0 = fmaf(-2.0f, lo + hi, eqa) + csA;
                upk2(lo, hi, dAb); float distA1 = fmaf(-2.0f, lo + hi, eqb) + csA;
                upk2(lo, hi, dBa); float distB0 = fmaf(-2.0f, lo + hi, eqa) + csB;
                upk2(lo, hi, dBb); float distB1 = fmaf(-2.0f, lo + hi, eqb) + csB;

                if (distA0 < bA0) { bA0 = distA0; iA0 = s; }
                if (distA1 < bA1) { bA1 = distA1; iA1 = s; }
                if (distB0 < bB0) { bB0 = distB0; iB0 = s + 1; }
                if (distB1 < bB1) { bB1 = distB1; iB1 = s + 1; }
            }
            // merge even/odd chains with exact first-index tie-break
            if (bB0 < bA0 || (bB0 == bA0 && iB0 < iA0)) { bA0 = bB0; iA0 = iB0; }
            if (bB1 < bA1 || (bB1 == bA1 && iB1 < iA1)) { bA1 = bB1; iA1 = iB1; }
            sm.redb[ch][2 * tp]     = bA0;  sm.redi[ch][2 * tp]     = iA0;
            sm.redb[ch][2 * tp + 1] = bA1;  sm.redi[ch][2 * tp + 1] = iA1;
        }
        __syncthreads();

        // ---- reduce 16 chunks per t ----
        if (tid < TTILE) {
            float bb = sm.redb[0][tid]; int bi = sm.redi[0][tid];
            #pragma unroll
            for (int g = 1; g < 16; g++) {
                float v = sm.redb[g][tid];
                if (v < bb) { bb = v; bi = sm.redi[g][tid]; }  // chunks ascending
            }
            sm.idx[tid] = bi;
            out_codes[((size_t)b * NQ + q) * TT + t0 + tid] = (float)bi;
        }
        __syncthreads();

        // ---- z_q = z_i + (raw - z_i)  (mapping A, ziv in register) ----
        {
            int sidx = sm.idx[tA];
            float raw = __ldg(&cbraw[((size_t)q * CS + sidx) * CD + cA]);
            float zqv = ziv + (raw - ziv);
            sm.zqs[cA][tA] = zqv;
            out_zqs[(((size_t)b * NQ + q) * CD + cA) * TT + t0 + tA] = zqv;
        }
        __syncthreads();

        // ---- z_o = w_out @ z_q + ob ; residual -= z_o  (mapping E, packed d) ----
        {
            ull zp[8];
            #pragma unroll
            for (int c = 0; c < CD; c++) {
                float v = sm.zqs[c][tE];
                zp[c] = pk2(v, v);
            }
            float* rrow = &sm.rest[tE * RPITCH];
            float* zob = out_zos + (((size_t)b * NQ + q) * DD) * TT + t0 + tE;
            const ull NEG1 = pk2(-1.0f, -1.0f);
            const int d0 = dg * 64;
            #pragma unroll 4
            for (int d = d0; d < d0 + 64; d += 4) {
                ull a01 = 0ull, a23 = 0ull;
                #pragma unroll
                for (int c = 0; c < CD; c++) {
                    ulonglong2 wc = *reinterpret_cast<const ulonglong2*>(&sm.woutT[c][d]);
                    a01 = fma2(zp[c], wc.x, a01);
                    a23 = fma2(zp[c], wc.y, a23);
                }
                ulonglong2 obp = *reinterpret_cast<const ulonglong2*>(&sm.ob[d]);
                ull zo01 = add2(a01, obp.x);
                ull zo23 = add2(a23, obp.y);
                float z0, z1, z2, z3;
                upk2(z0, z1, zo01); upk2(z2, z3, zo23);
                zob[(size_t)(d + 0) * TT] = z0;
                zob[(size_t)(d + 1) * TT] = z1;
                zob[(size_t)(d + 2) * TT] = z2;
                zob[(size_t)(d + 3) * TT] = z3;
                ull r01 = *reinterpret_cast<const ull*>(rrow + d);
                ull r23 = *reinterpret_cast<const ull*>(rrow + d + 2);
                r01 = fma2(zo01, NEG1, r01);
                r23 = fma2(zo23, NEG1, r23);
                *reinterpret_cast<ull*>(rrow + d) = r01;
                *reinterpret_cast<ull*>(rrow + d + 2) = r23;
            }
        }
    }

    __syncthreads();
    // ---- z_O = z - residual_final  (mapping E) ----
    {
        const float* zsrc = zb + tE;
        float* zOb = out_zO + (size_t)b * DD * TT + t0 + tE;
        const float* rrow = &sm.rest[tE * RPITCH];
        const int d0 = dg * 64;
        #pragma unroll 8
        for (int d = d0; d < d0 + 64; d++) {
            zOb[(size_t)d * TT] = zsrc[(size_t)d * TT] - rrow[d];
        }
    }
}

extern "C" void kernel_launch(void* const* d_in, const int* in_sizes, int n_in,
                              void* d_out, int out_size) {
    const float* z    = (const float*)d_in[0];
    const float* in_v = (const float*)d_in[1];
    const float* in_g = (const float*)d_in[2];
    const float* in_b = (const float*)d_in[3];
    const float* out_v= (const float*)d_in[4];
    const float* out_g= (const float*)d_in[5];
    const float* out_b= (const float*)d_in[6];
    const float* cb   = (const float*)d_in[7];
    float* out = (float*)d_out;

    rvq_precompute<<<NQ, 256>>>(in_v, in_g, out_v, out_g, cb);

    cudaFuncSetAttribute(rvq_kernel, cudaFuncAttributeMaxDynamicSharedMemorySize,
                         (int)sizeof(SMem));
    dim3 grid(TT / TTILE, BB);
    rvq_kernel<<<grid, NTHREADS, sizeof(SMem)>>>(z, in_b, out_b, cb, out);
}

// round 3
// speedup vs baseline: 1.0457x; 1.0457x over previous
#include <cuda_runtime.h>
#include <math.h>
#include <float.h>
#include <stdint.h>

#define BB 16
#define DD 512
#define TT 2048
#define NQ 9
#define CS 1024
#define CD 8
#define TTILE 64
#define NTHREADS 512
#define RP 68   // res row pitch (floats): 68 % 32 == 4 -> dg-lane banks 4*dg+t distinct

typedef unsigned long long ull;

__device__ __forceinline__ ull pk2(float lo, float hi) {
    ull r; asm("mov.b64 %0,{%1,%2};" : "=l"(r) : "f"(lo), "f"(hi)); return r;
}
__device__ __forceinline__ void upk2(float& lo, float& hi, ull v) {
    asm("mov.b64 {%0,%1},%2;" : "=f"(lo), "=f"(hi) : "l"(v));
}
__device__ __forceinline__ ull fma2(ull a, ull b, ull c) {
    ull d; asm("fma.rn.f32x2 %0,%1,%2,%3;" : "=l"(d) : "l"(a), "l"(b), "l"(c)); return d;
}

// ---------------- precomputed (normalized) parameter scratch ----------------
__device__ float g_winT[NQ * DD * CD];  // weight-normed in_proj, d-major (q, d, c)
__device__ float g_wout[NQ * DD * CD];  // weight-normed out_proj (q, d, c)
__device__ float g_cbn[NQ * CS * CD];   // l2-normalized codebook
__device__ float g_csq[NQ * CS];        // sum(c_norm^2) per code

__global__ void rvq_precompute(const float* __restrict__ iv, const float* __restrict__ ig,
                               const float* __restrict__ ov, const float* __restrict__ og,
                               const float* __restrict__ cb) {
    int q = blockIdx.x;
    int tid = threadIdx.x;           // 256 threads
    int wid = tid >> 5, lane = tid & 31;

    // in_proj: 8 rows of 512, one warp per row; store TRANSPOSED (d-major)
    if (wid < CD) {
        int c = wid;
        const float* v = iv + ((size_t)q * CD + c) * DD;
        float ss = 0.f;
        for (int d = lane; d < DD; d += 32) { float x = v[d]; ss = fmaf(x, x, ss); }
        #pragma unroll
        for (int o = 16; o > 0; o >>= 1) ss += __shfl_xor_sync(0xffffffffu, ss, o);
        float nrm = __fsqrt_rn(ss);
        float g = ig[q * CD + c];
        for (int d = lane; d < DD; d += 32)
            g_winT[((size_t)q * DD + d) * CD + c] = __fdiv_rn(g * v[d], nrm);
    }
    // out_proj: 512 rows of 8 (d-major, as consumed by z_o)
    for (int r = tid; r < DD; r += 256) {
        const float* v = ov + ((size_t)q * DD + r) * CD;
        float ss = 0.f;
        #pragma unroll
        for (int c = 0; c < CD; c++) { float x = v[c]; ss = fmaf(x, x, ss); }
        float nrm = __fsqrt_rn(ss);
        float g = og[q * DD + r];
        #pragma unroll
        for (int c = 0; c < CD; c++)
            g_wout[((size_t)q * DD + r) * CD + c] = __fdiv_rn(g * v[c], nrm);
    }
    // codebook: 1024 rows of 8, l2norm with eps, plus csq
    for (int s = tid; s < CS; s += 256) {
        const float* v = cb + ((size_t)q * CS + s) * CD;
        float ss = 0.f;
        #pragma unroll
        for (int c = 0; c < CD; c++) { float x = v[c]; ss = fmaf(x, x, ss); }
        float den = fmaxf(__fsqrt_rn(ss), 1e-12f);
        float cs2 = 0.f;
        #pragma unroll
        for (int c = 0; c < CD; c++) {
            float cn = __fdiv_rn(v[c], den);
            g_cbn[((size_t)q * CS + s) * CD + c] = cn;
            cs2 = fmaf(cn, cn, cs2);
        }
        g_csq[q * CS + s] = cs2;
    }
}

// ---------------- main fused RVQ kernel ----------------
struct SMem {
    float4 cbn4[CS * 2];         // 32768  normalized codebook
    float  res[DD * RP];         // 139264 residual [d][t], pitch 68
    float4 winT[DD * 2];         // 16384  in_proj d-major (2 float4 = 8 c per d)
    float  wout[DD * CD];        // 16384  out_proj d-major
    float  csq[CS];              // 4096
    float  ob[DD];               // 2048
    float  zi[CD][RP];           // 2176
    float  enc[CD][RP];          // 2176
    float  zqs[CD][RP];          // 2176
    float  redb[8][RP];          // 2176
    int    redi[8][RP];          // 2176
    float  encsq[TTILE];         // 256
    int    idx[TTILE];           // 256
    float  ib[CD];               // 32
};  // ~217 KB

__device__ __forceinline__ float dist8(float4 ca, float4 cb2,
                                       float e0, float e1, float e2, float e3,
                                       float e4, float e5, float e6, float e7,
                                       float eq, float cs) {
    float dot = e0 * ca.x;
    dot = fmaf(e1, ca.y, dot); dot = fmaf(e2, ca.z, dot); dot = fmaf(e3, ca.w, dot);
    dot = fmaf(e4, cb2.x, dot); dot = fmaf(e5, cb2.y, dot);
    dot = fmaf(e6, cb2.z, dot); dot = fmaf(e7, cb2.w, dot);
    return fmaf(-2.0f, dot, eq) + cs;
}

__global__ void __launch_bounds__(NTHREADS, 1)
rvq_kernel(const float* __restrict__ z,
           const float* __restrict__ ib_g,
           const float* __restrict__ ob_g,
           const float* __restrict__ cbraw,
           float* __restrict__ out) {
    extern __shared__ unsigned char smraw[];
    SMem& sm = *reinterpret_cast<SMem*>(smraw);

    const int tid = threadIdx.x;
    const int b = blockIdx.y;
    const int t0 = blockIdx.x * TTILE;

    float* out_codes = out;
    float* out_zO  = out + (size_t)BB * NQ * TT;
    float* out_zis = out_zO + (size_t)BB * DD * TT;
    float* out_zqs = out_zis + (size_t)BB * NQ * CD * TT;
    float* out_zos = out_zqs + (size_t)BB * NQ * CD * TT;

    // ---- load residual tile into res[d][t] (pitch RP) ----
    const float* zb = z + (size_t)b * DD * TT + t0;
    for (int f = tid; f < DD * (TTILE / 4); f += NTHREADS) {
        int d = f >> 4, j = f & 15;
        float4 v = reinterpret_cast<const float4*>(zb + (size_t)d * TT)[j];
        float* r = &sm.res[d * RP + 4 * j];
        r[0] = v.x; r[1] = v.y; r[2] = v.z; r[3] = v.w;
    }

    // z_i mapping: dg = tid&7 (d-interleave), tz = tid>>3
    const int dgz = tid & 7;
    const int tz  = tid >> 3;
    // lane after reduce holds channel cZ (bit-reversed dg)
    const int cZ = ((dgz & 1) << 2) | (dgz & 2) | (dgz >> 2);
    // NN mapping: hi = chunk, t = tid&63
    const int hi = tid >> 6;
    const int t  = tid & 63;

    for (int q = 0; q < NQ; q++) {
        __syncthreads();   // res settled, previous tables free
        // ---- load per-quantizer tables ----
        {
            const float4* s1 = reinterpret_cast<const float4*>(g_winT + (size_t)q * DD * CD);
            for (int i = tid; i < DD * 2; i += NTHREADS) sm.winT[i] = s1[i];
            const float4* s2 = reinterpret_cast<const float4*>(g_wout + (size_t)q * DD * CD);
            float4* d2 = reinterpret_cast<float4*>(&sm.wout[0]);
            for (int i = tid; i < DD * CD / 4; i += NTHREADS) d2[i] = s2[i];
            const float4* s3 = reinterpret_cast<const float4*>(g_cbn + (size_t)q * CS * CD);
            for (int i = tid; i < CS * 2; i += NTHREADS) sm.cbn4[i] = s3[i];
            const float4* s4 = reinterpret_cast<const float4*>(g_csq + (size_t)q * CS);
            float4* d4 = reinterpret_cast<float4*>(&sm.csq[0]);
            for (int i = tid; i < CS / 4; i += NTHREADS) d4[i] = s4[i];
            const float4* s5 = reinterpret_cast<const float4*>(ob_g + (size_t)q * DD);
            float4* d5 = reinterpret_cast<float4*>(&sm.ob[0]);
            for (int i = tid; i < DD / 4; i += NTHREADS) d5[i] = s5[i];
            if (tid < CD) sm.ib[tid] = ib_g[q * CD + tid];
        }
        __syncthreads();

        // ---- z_i: thread (dgz,tz) does 8 channels over d = 8i+dgz ----
        float ziv;
        {
            const ulonglong2* wt = reinterpret_cast<const ulonglong2*>(sm.winT);
            ull a01 = 0ull, a23 = 0ull, a45 = 0ull, a67 = 0ull;
            #pragma unroll 8
            for (int i = 0; i < 64; i++) {
                int d = (i << 3) | dgz;
                float r = sm.res[d * RP + tz];       // 1 phase (banks 4*dgz+tz)
                ull rr = pk2(r, r);
                ulonglong2 wa = wt[2 * d];           // c0..c3 (broadcast per dg)
                ulonglong2 wb = wt[2 * d + 1];       // c4..c7
                a01 = fma2(rr, wa.x, a01);
                a23 = fma2(rr, wa.y, a23);
                a45 = fma2(rr, wb.x, a45);
                a67 = fma2(rr, wb.y, a67);
            }
            float s[8];
            upk2(s[0], s[1], a01); upk2(s[2], s[3], a23);
            upk2(s[4], s[5], a45); upk2(s[6], s[7], a67);

            // shuffle tree over dg bits: reduce d-partials, split channels
            {
                int bsel = dgz & 1;
                #pragma unroll
                for (int j = 0; j < 4; j++) {
                    float v = bsel ? s[j] : s[4 + j];
                    float o = __shfl_xor_sync(0xffffffffu, v, 1);
                    s[j] = (bsel ? s[4 + j] : s[j]) + o;
                }
                bsel = dgz & 2;
                #pragma unroll
                for (int j = 0; j < 2; j++) {
                    float v = bsel ? s[j] : s[2 + j];
                    float o = __shfl_xor_sync(0xffffffffu, v, 2);
                    s[j] = (bsel ? s[2 + j] : s[j]) + o;
                }
                bsel = dgz & 4;
                {
                    float v = bsel ? s[0] : s[1];
                    float o = __shfl_xor_sync(0xffffffffu, v, 4);
                    s[0] = (bsel ? s[1] : s[0]) + o;
                }
            }
            ziv = s[0] + sm.ib[cZ];
            sm.zi[cZ][tz] = ziv;
            out_zis[(((size_t)b * NQ + q) * CD + cZ) * TT + t0 + tz] = ziv;

            // L2-norm across the 8 dg-lanes (they hold the 8 channels of tz)
            float ss = ziv * ziv;
            ss += __shfl_xor_sync(0xffffffffu, ss, 1);
            ss += __shfl_xor_sync(0xffffffffu, ss, 2);
            ss += __shfl_xor_sync(0xffffffffu, ss, 4);
            float den = fmaxf(__fsqrt_rn(ss), 1e-12f);
            float e = __fdiv_rn(ziv, den);
            float es = e * e;
            es += __shfl_xor_sync(0xffffffffu, es, 1);
            es += __shfl_xor_sync(0xffffffffu, es, 2);
            es += __shfl_xor_sync(0xffffffffu, es, 4);
            sm.enc[cZ][tz] = e;
            if (dgz == 0) sm.encsq[tz] = es;
        }
        __syncthreads();

        // ---- NN search: chunk=hi (128 codes), t column ----
        {
            const float e0 = sm.enc[0][t], e1 = sm.enc[1][t], e2 = sm.enc[2][t], e3 = sm.enc[3][t];
            const float e4 = sm.enc[4][t], e5 = sm.enc[5][t], e6 = sm.enc[6][t], e7 = sm.enc[7][t];
            const float eq = sm.encsq[t];
            const int s0 = hi * (CS / 8);
            float b0 = FLT_MAX, b1 = FLT_MAX, b2 = FLT_MAX, b3 = FLT_MAX;
            int   i0 = 0, i1 = 0, i2 = 0, i3 = 0;
            #pragma unroll 2
            for (int s = s0; s < s0 + CS / 8; s += 4) {
                float dA = dist8(sm.cbn4[2 * s + 0], sm.cbn4[2 * s + 1], e0,e1,e2,e3,e4,e5,e6,e7, eq, sm.csq[s + 0]);
                float dB = dist8(sm.cbn4[2 * s + 2], sm.cbn4[2 * s + 3], e0,e1,e2,e3,e4,e5,e6,e7, eq, sm.csq[s + 1]);
                float dC = dist8(sm.cbn4[2 * s + 4], sm.cbn4[2 * s + 5], e0,e1,e2,e3,e4,e5,e6,e7, eq, sm.csq[s + 2]);
                float dDv= dist8(sm.cbn4[2 * s + 6], sm.cbn4[2 * s + 7], e0,e1,e2,e3,e4,e5,e6,e7, eq, sm.csq[s + 3]);
                if (dA < b0) { b0 = dA; i0 = s; }
                if (dB < b1) { b1 = dB; i1 = s + 1; }
                if (dC < b2) { b2 = dC; i2 = s + 2; }
                if (dDv< b3) { b3 = dDv; i3 = s + 3; }
            }
            if (b1 < b0 || (b1 == b0 && i1 < i0)) { b0 = b1; i0 = i1; }
            if (b2 < b0 || (b2 == b0 && i2 < i0)) { b0 = b2; i0 = i2; }
            if (b3 < b0 || (b3 == b0 && i3 < i0)) { b0 = b3; i0 = i3; }
            sm.redb[hi][t] = b0;
            sm.redi[hi][t] = i0;
        }
        __syncthreads();
        if (tid < TTILE) {
            float bb = sm.redb[0][tid]; int bi = sm.redi[0][tid];
            #pragma unroll
            for (int g = 1; g < 8; g++) {
                float v = sm.redb[g][tid];
                if (v < bb) { bb = v; bi = sm.redi[g][tid]; }
            }
            sm.idx[tid] = bi;
            out_codes[((size_t)b * NQ + q) * TT + t0 + tid] = (float)bi;
        }
        __syncthreads();

        // ---- z_q = z_i + (raw - z_i)  (c = hi, t) ----
        {
            int sidx = sm.idx[t];
            float zival = sm.zi[hi][t];
            float raw = __ldg(&cbraw[((size_t)q * CS + sidx) * CD + hi]);
            float zqv = zival + (raw - zival);
            sm.zqs[hi][t] = zqv;
            out_zqs[(((size_t)b * NQ + q) * CD + hi) * TT + t0 + t] = zqv;
        }
        __syncthreads();

        // ---- z_o = w_out @ z_q + ob ; residual -= z_o  (dgroup=hi, t) ----
        {
            const float q0 = sm.zqs[0][t], q1 = sm.zqs[1][t], q2 = sm.zqs[2][t], q3 = sm.zqs[3][t];
            const float q4 = sm.zqs[4][t], q5 = sm.zqs[5][t], q6 = sm.zqs[6][t], q7 = sm.zqs[7][t];
            const float4* wo4 = reinterpret_cast<const float4*>(&sm.wout[0]);
            float* zosb = out_zos + (((size_t)b * NQ + q) * DD) * TT + t0 + t;
            const int dbase = hi * 64;
            #pragma unroll 4
            for (int i = 0; i < 64; i++) {
                int d = dbase + i;
                float4 wa = wo4[2 * d], wb = wo4[2 * d + 1];
                float dot = q0 * wa.x;
                dot = fmaf(q1, wa.y, dot); dot = fmaf(q2, wa.z, dot); dot = fmaf(q3, wa.w, dot);
                dot = fmaf(q4, wb.x, dot); dot = fmaf(q5, wb.y, dot);
                dot = fmaf(q6, wb.z, dot); dot = fmaf(q7, wb.w, dot);
                float zo = dot + sm.ob[d];
                zosb[(size_t)d * TT] = zo;
                sm.res[d * RP + t] -= zo;
            }
        }
    }

    __syncthreads();
    // ---- z_O = z - residual_final ----
    {
        const float* zsrc = zb + t;
        float* zOb = out_zO + (size_t)b * DD * TT + t0 + t;
        const int dbase = hi * 64;
        #pragma unroll 4
        for (int i = 0; i < 64; i++) {
            int d = dbase + i;
            zOb[(size_t)d * TT] = zsrc[(size_t)d * TT] - sm.res[d * RP + t];
        }
    }
}

extern "C" void kernel_launch(void* const* d_in, const int* in_sizes, int n_in,
                              void* d_out, int out_size) {
    const float* z    = (const float*)d_in[0];
    const float* in_v = (const float*)d_in[1];
    const float* in_g = (const float*)d_in[2];
    const float* in_b = (const float*)d_in[3];
    const float* out_v= (const float*)d_in[4];
    const float* out_g= (const float*)d_in[5];
    const float* out_b= (const float*)d_in[6];
    const float* cb   = (const float*)d_in[7];
    float* out = (float*)d_out;

    rvq_precompute<<<NQ, 256>>>(in_v, in_g, out_v, out_g, cb);

    cudaFuncSetAttribute(rvq_kernel, cudaFuncAttributeMaxDynamicSharedMemorySize,
                         (int)sizeof(SMem));
    dim3 grid(TT / TTILE, BB);
    rvq_kernel<<<grid, NTHREADS, sizeof(SMem)>>>(z, in_b, out_b, cb, out);
}

// round 5
// speedup vs baseline: 1.1489x; 1.0987x over previous
#include <cuda_runtime.h>
#include <math.h>
#include <float.h>
#include <stdint.h>

#define BB 16
#define DD 512
#define TT 2048
#define NQ 9
#define CS 1024
#define CD 8
#define TTILE 64
#define NTHREADS 512

// ---------------- precomputed (normalized) parameter scratch ----------------
__device__ float g_win[NQ * CD * DD];   // weight-normed in_proj  (q, c, d)
__device__ float g_wout[NQ * DD * CD];  // weight-normed out_proj (q, d, c)
__device__ float g_cbn[NQ * CS * CD];   // l2-normalized codebook
__device__ float g_csq[NQ * CS];        // sum(c_norm^2) per code

__global__ void rvq_precompute(const float* __restrict__ iv, const float* __restrict__ ig,
                               const float* __restrict__ ov, const float* __restrict__ og,
                               const float* __restrict__ cb) {
    int q = blockIdx.x;
    int tid = threadIdx.x;           // 256 threads
    int wid = tid >> 5, lane = tid & 31;

    // in_proj: 8 rows of 512, one warp per row
    if (wid < CD) {
        int c = wid;
        const float* v = iv + ((size_t)q * CD + c) * DD;
        float ss = 0.f;
        for (int d = lane; d < DD; d += 32) { float x = v[d]; ss = fmaf(x, x, ss); }
        #pragma unroll
        for (int o = 16; o > 0; o >>= 1) ss += __shfl_xor_sync(0xffffffffu, ss, o);
        float nrm = __fsqrt_rn(ss);
        float g = ig[q * CD + c];
        for (int d = lane; d < DD; d += 32)
            g_win[((size_t)q * CD + c) * DD + d] = __fdiv_rn(g * v[d], nrm);
    }
    // out_proj: 512 rows of 8
    for (int r = tid; r < DD; r += 256) {
        const float* v = ov + ((size_t)q * DD + r) * CD;
        float ss = 0.f;
        #pragma unroll
        for (int c = 0; c < CD; c++) { float x = v[c]; ss = fmaf(x, x, ss); }
        float nrm = __fsqrt_rn(ss);
        float g = og[q * DD + r];
        #pragma unroll
        for (int c = 0; c < CD; c++)
            g_wout[((size_t)q * DD + r) * CD + c] = __fdiv_rn(g * v[c], nrm);
    }
    // codebook: 1024 rows of 8, l2norm with eps, plus csq
    for (int s = tid; s < CS; s += 256) {
        const float* v = cb + ((size_t)q * CS + s) * CD;
        float ss = 0.f;
        #pragma unroll
        for (int c = 0; c < CD; c++) { float x = v[c]; ss = fmaf(x, x, ss); }
        float den = fmaxf(__fsqrt_rn(ss), 1e-12f);
        float cs2 = 0.f;
        #pragma unroll
        for (int c = 0; c < CD; c++) {
            float cn = __fdiv_rn(v[c], den);
            g_cbn[((size_t)q * CS + s) * CD + c] = cn;
            cs2 = fmaf(cn, cn, cs2);
        }
        g_csq[q * CS + s] = cs2;
    }
}

// ---------------- main fused RVQ kernel ----------------
struct SMem {
    float4 cbn4[CS * 2];        // 32 KB  normalized codebook (2 float4 per code)
    float  res[DD][TTILE];      // 128 KB residual tile
    float  win[CD][DD];         // 16 KB
    float  wout[DD][CD];        // 16 KB
    float4 csq4[CS / 4];        // 4 KB
    float  ob[DD];              // 2 KB
    float  zi[CD][TTILE];       // 2 KB
    float  zqs[CD][TTILE];      // 2 KB
    float  redb[8][TTILE];      // 2 KB
    int    redi[8][TTILE];      // 2 KB
    float  ib[CD];
};  // ~206 KB

__device__ __forceinline__ float dist8(float4 ca, float4 cb2,
                                       float e0, float e1, float e2, float e3,
                                       float e4, float e5, float e6, float e7,
                                       float eq, float cs) {
    float dot = e0 * ca.x;
    dot = fmaf(e1, ca.y, dot); dot = fmaf(e2, ca.z, dot); dot = fmaf(e3, ca.w, dot);
    dot = fmaf(e4, cb2.x, dot); dot = fmaf(e5, cb2.y, dot);
    dot = fmaf(e6, cb2.z, dot); dot = fmaf(e7, cb2.w, dot);
    // matches reference ((enc_sq - 2*dot) + csq)
    return fmaf(-2.0f, dot, eq) + cs;
}

__global__ void __launch_bounds__(NTHREADS, 1)
rvq_kernel(const float* __restrict__ z,
           const float* __restrict__ ib_g,
           const float* __restrict__ ob_g,
           const float* __restrict__ cbraw,
           float* __restrict__ out) {
    extern __shared__ unsigned char smraw[];
    SMem& sm = *reinterpret_cast<SMem*>(smraw);

    const int tid = threadIdx.x;
    const int b = blockIdx.y;
    const int t0 = blockIdx.x * TTILE;

    float* out_codes = out;
    float* out_zO  = out + (size_t)BB * NQ * TT;
    float* out_zis = out_zO + (size_t)BB * DD * TT;
    float* out_zqs = out_zis + (size_t)BB * NQ * CD * TT;
    float* out_zos = out_zqs + (size_t)BB * NQ * CD * TT;

    // ---- load residual tile (vectorized) ----
    const float* zb = z + (size_t)b * DD * TT + t0;
    {
        float4* res4 = reinterpret_cast<float4*>(&sm.res[0][0]);
        for (int f = tid; f < DD * (TTILE / 4); f += NTHREADS) {
            int d = f >> 4, j = f & 15;
            res4[f] = reinterpret_cast<const float4*>(zb + (size_t)d * TT)[j];
        }
    }

    const int t  = tid & (TTILE - 1);   // 0..63
    const int hi = tid >> 6;            // 0..7  (c / chunk / d-group depending on phase)

    for (int q = 0; q < NQ; q++) {
        __syncthreads();   // res settled; previous-q table use done
        // ---- load per-quantizer tables ----
        {
            const float4* s1 = reinterpret_cast<const float4*>(g_win + (size_t)q * CD * DD);
            float4* d1 = reinterpret_cast<float4*>(&sm.win[0][0]);
            for (int i = tid; i < CD * DD / 4; i += NTHREADS) d1[i] = s1[i];
            const float4* s2 = reinterpret_cast<const float4*>(g_wout + (size_t)q * DD * CD);
            float4* d2 = reinterpret_cast<float4*>(&sm.wout[0][0]);
            for (int i = tid; i < DD * CD / 4; i += NTHREADS) d2[i] = s2[i];
            const float4* s3 = reinterpret_cast<const float4*>(g_cbn + (size_t)q * CS * CD);
            for (int i = tid; i < CS * 2; i += NTHREADS) sm.cbn4[i] = s3[i];
            const float4* s4 = reinterpret_cast<const float4*>(g_csq + (size_t)q * CS);
            for (int i = tid; i < CS / 4; i += NTHREADS) sm.csq4[i] = s4[i];
            const float4* s5 = reinterpret_cast<const float4*>(ob_g + (size_t)q * DD);
            float4* d5 = reinterpret_cast<float4*>(&sm.ob[0]);
            for (int i = tid; i < DD / 4; i += NTHREADS) d5[i] = s5[i];
            if (tid < CD) sm.ib[tid] = ib_g[q * CD + tid];
        }
        __syncthreads();

        // ---- z_i = w_in @ residual + ib  (thread = (c=hi, t)) ----
        float ziv;
        {
            const int c = hi;
            const float4* wr4 = reinterpret_cast<const float4*>(sm.win[c]);
            float a0 = 0.f, a1 = 0.f, a2 = 0.f, a3 = 0.f;
            #pragma unroll 4
            for (int i = 0; i < DD / 4; i++) {
                float4 w = wr4[i];                  // broadcast LDS.128
                int d = 4 * i;
                a0 = fmaf(w.x, sm.res[d + 0][t], a0);
                a1 = fmaf(w.y, sm.res[d + 1][t], a1);
                a2 = fmaf(w.z, sm.res[d + 2][t], a2);
                a3 = fmaf(w.w, sm.res[d + 3][t], a3);
            }
            ziv = ((a0 + a1) + (a2 + a3)) + sm.ib[c];
            sm.zi[c][t] = ziv;
            out_zis[(((size_t)b * NQ + q) * CD + c) * TT + t0 + t] = ziv;
        }
        __syncthreads();

        // ---- NN search: redundant per-thread norm, then 128 codes (chunk=hi) ----
        {
            // per-column L2 norm (same summation order as reference)
            float z0 = sm.zi[0][t], z1 = sm.zi[1][t], z2 = sm.zi[2][t], z3 = sm.zi[3][t];
            float z4 = sm.zi[4][t], z5 = sm.zi[5][t], z6 = sm.zi[6][t], z7 = sm.zi[7][t];
            float ss = z0 * z0;
            ss = fmaf(z1, z1, ss); ss = fmaf(z2, z2, ss); ss = fmaf(z3, z3, ss);
            ss = fmaf(z4, z4, ss); ss = fmaf(z5, z5, ss); ss = fmaf(z6, z6, ss);
            ss = fmaf(z7, z7, ss);
            float den = fmaxf(__fsqrt_rn(ss), 1e-12f);
            float e0 = __fdiv_rn(z0, den), e1 = __fdiv_rn(z1, den);
            float e2 = __fdiv_rn(z2, den), e3 = __fdiv_rn(z3, den);
            float e4 = __fdiv_rn(z4, den), e5 = __fdiv_rn(z5, den);
            float e6 = __fdiv_rn(z6, den), e7 = __fdiv_rn(z7, den);
            float eq = e0 * e0;
            eq = fmaf(e1, e1, eq); eq = fmaf(e2, e2, eq); eq = fmaf(e3, e3, eq);
            eq = fmaf(e4, e4, eq); eq = fmaf(e5, e5, eq); eq = fmaf(e6, e6, eq);
            eq = fmaf(e7, e7, eq);

            const int s0 = hi * (CS / 8);
            float b0 = FLT_MAX, b1 = FLT_MAX, b2 = FLT_MAX, b3 = FLT_MAX;
            int   i0 = 0, i1 = 0, i2 = 0, i3 = 0;
            #pragma unroll 2
            for (int s = s0; s < s0 + CS / 8; s += 4) {
                float4 cs4 = sm.csq4[s >> 2];       // broadcast LDS.128, 4 codes
                float dA = dist8(sm.cbn4[2 * s + 0], sm.cbn4[2 * s + 1], e0,e1,e2,e3,e4,e5,e6,e7, eq, cs4.x);
                float dB = dist8(sm.cbn4[2 * s + 2], sm.cbn4[2 * s + 3], e0,e1,e2,e3,e4,e5,e6,e7, eq, cs4.y);
                float dC = dist8(sm.cbn4[2 * s + 4], sm.cbn4[2 * s + 5], e0,e1,e2,e3,e4,e5,e6,e7, eq, cs4.z);
                float dDv= dist8(sm.cbn4[2 * s + 6], sm.cbn4[2 * s + 7], e0,e1,e2,e3,e4,e5,e6,e7, eq, cs4.w);
                if (dA < b0) { b0 = dA; i0 = s; }
                if (dB < b1) { b1 = dB; i1 = s + 1; }
                if (dC < b2) { b2 = dC; i2 = s + 2; }
                if (dDv< b3) { b3 = dDv; i3 = s + 3; }
            }
            // merge 4 strided chains, exact first-index tie-break
            if (b1 < b0 || (b1 == b0 && i1 < i0)) { b0 = b1; i0 = i1; }
            if (b2 < b0 || (b2 == b0 && i2 < i0)) { b0 = b2; i0 = i2; }
            if (b3 < b0 || (b3 == b0 && i3 < i0)) { b0 = b3; i0 = i3; }
            sm.redb[hi][t] = b0;
            sm.redi[hi][t] = i0;
        }
        __syncthreads();

        // ---- z_q: redundant argmin merge + straight-through  (thread = (c=hi, t)) ----
        {
            float bb = sm.redb[0][t]; int bi = sm.redi[0][t];
            #pragma unroll
            for (int g = 1; g < 8; g++) {
                float v = sm.redb[g][t];
                if (v < bb) { bb = v; bi = sm.redi[g][t]; }   // chunks ascending
            }
            if (hi == 0)
                out_codes[((size_t)b * NQ + q) * TT + t0 + t] = (float)bi;
            float raw = __ldg(&cbraw[((size_t)q * CS + bi) * CD + hi]);
            float zqv = ziv + (raw - ziv);
            sm.zqs[hi][t] = zqv;
            out_zqs[(((size_t)b * NQ + q) * CD + hi) * TT + t0 + t] = zqv;
        }
        __syncthreads();

        // ---- z_o = w_out @ z_q + ob ; residual -= z_o  (thread = (dgroup=hi, t)) ----
        {
            const float q0 = sm.zqs[0][t], q1 = sm.zqs[1][t], q2 = sm.zqs[2][t], q3 = sm.zqs[3][t];
            const float q4 = sm.zqs[4][t], q5 = sm.zqs[5][t], q6 = sm.zqs[6][t], q7 = sm.zqs[7][t];
            const float4* wo4 = reinterpret_cast<const float4*>(&sm.wout[0][0]);
            float* zosb = out_zos + (((size_t)b * NQ + q) * DD) * TT + t0 + t;
            const int dbase = hi * 64;
            #pragma unroll 4
            for (int i = 0; i < 64; i++) {
                int d = dbase + i;
                float4 wa = wo4[2 * d], wb = wo4[2 * d + 1];
                float dot = q0 * wa.x;
                dot = fmaf(q1, wa.y, dot); dot = fmaf(q2, wa.z, dot); dot = fmaf(q3, wa.w, dot);
                dot = fmaf(q4, wb.x, dot); dot = fmaf(q5, wb.y, dot);
                dot = fmaf(q6, wb.z, dot); dot = fmaf(q7, wb.w, dot);
                float zo = dot + sm.ob[d];
                zosb[(size_t)d * TT] = zo;
                sm.res[d][t] = sm.res[d][t] - zo;
            }
        }
    }

    __syncthreads();
    // ---- z_O = z - residual_final ----
    {
        const float* zsrc = zb + t;
        float* zOb = out_zO + (size_t)b * DD * TT + t0 + t;
        const int dbase = hi * 64;
        #pragma unroll 4
        for (int i = 0; i < 64; i++) {
            int d = dbase + i;
            zOb[(size_t)d * TT] = zsrc[(size_t)d * TT] - sm.res[d][t];
        }
    }
}

extern "C" void kernel_launch(void* const* d_in, const int* in_sizes, int n_in,
                              void* d_out, int out_size) {
    const float* z    = (const float*)d_in[0];
    const float* in_v = (const float*)d_in[1];
    const float* in_g = (const float*)d_in[2];
    const float* in_b = (const float*)d_in[3];
    const float* out_v= (const float*)d_in[4];
    const float* out_g= (const float*)d_in[5];
    const float* out_b= (const float*)d_in[6];
    const float* cb   = (const float*)d_in[7];
    float* out = (float*)d_out;

    rvq_precompute<<<NQ, 256>>>(in_v, in_g, out_v, out_g, cb);

    cudaFuncSetAttribute(rvq_kernel, cudaFuncAttributeMaxDynamicSharedMemorySize,
                         (int)sizeof(SMem));
    dim3 grid(TT / TTILE, BB);
    rvq_kernel<<<grid, NTHREADS, sizeof(SMem)>>>(z, in_b, out_b, cb, out);
}